// round 17
// baseline (speedup 1.0000x reference)
#include <cuda_runtime.h>
#include <cuda_fp16.h>
#include <cstdint>

// Problem constants
#define BB     64
#define CC     20
#define NAA    5
#define HHH    19
#define WWW    19
#define HW     361      // 19*19
#define TT     50
#define NBB    1280     // B*C
#define A4     1805     // NA*H*W
#define CHN    30       // NA*(5+NCPA)
#define EPS12  1e-12f
#define RB     4                              // rows per band
#define BANDS  5
#define TILE   (NAA * RB * WWW)               // 380 cells per band-block
#define TPB    96                             // 3 warps; 4 cells/thread
#define MAIN_BLOCKS (NBB * BANDS)             // 6400
#define CLS_N   (BB * A4)                     // 115520
#define CLS_BLOCKS ((CLS_N + TPB - 1) / TPB)  // 1204
#define TOTB    (MAIN_BLOCKS + CLS_BLOCKS)

// Static scratch (no allocations; self-cleaning or overwritten every run)
struct alignas(16) GTH { __half2 gl, gr, gt, gb; };
__device__ int    g_bm[NBB][BANDS];           // gts per (nb, band)
__device__ GTH    g_bgh[NBB][BANDS][TT];      // gt box, broadcast half2
__device__ __half2 g_bgc2[NBB][BANDS][TT];    // -0.375*area, broadcast half2
__device__ int    g_bn[NBB][BANDS];           // assignments per (nb, band)
__device__ int    g_bcell[NBB][BANDS][TT];
__device__ float  g_bval[NBB][BANDS][TT][5];  // tx, ty, tw, th, tconf
__device__ int    g_cnt[CLS_N];               // winners per (b, a4) across C
__device__ float  g_tsum[CLS_N];
__device__ float  g_accf[3];                  // dense, cls nll, nsel
__device__ unsigned int g_done;

__device__ __forceinline__ float fsigm(float v) {
    return __fdividef(1.0f, 1.0f + __expf(-v));
}

// ---------------------------------------------------------------------------
// One block (64 threads) per nb row. Computes gt boxes (converted to
// broadcast half2), winner assignments, and per-band compacted lists.
__global__ void k_assign(const float* __restrict__ out,
                         const float* __restrict__ target,
                         const float* __restrict__ anchors) {
    int nb = blockIdx.x;
    int t  = threadIdx.x;

    __shared__ float s_tg[TT * 5];
    __shared__ int   s_ng;
    __shared__ int   s_bm[BANDS], s_bn[BANDS];
    __shared__ int   s_cell[TT];

    if (t == 0) s_ng = TT;
    if (t < BANDS) { s_bm[t] = 0; s_bn[t] = 0; }
    const float* tg = target + (size_t)nb * TT * 5;
    for (int i = t; i < TT * 5; i += 64) s_tg[i] = tg[i];
    __syncthreads();

    if (t < TT && s_tg[t * 5 + 1] == 0.0f) atomicMin(&s_ng, t);
    __syncthreads();
    int ng = s_ng;

    float gx = 0.f, gy = 0.f, gw = 0.f, gh = 0.f, ct = 0.f;
    int gi = 0, gj = 0, bn = 0, cell = -1;
    float awb = 1.f, ahb = 1.f;

    if (t < ng) {
        ct = s_tg[t * 5 + 0];
        gx = s_tg[t * 5 + 1] * (float)WWW;
        gy = s_tg[t * 5 + 2] * (float)HHH;
        gw = s_tg[t * 5 + 3] * (float)WWW;
        gh = s_tg[t * 5 + 4] * (float)HHH;

        float best = -1.0f;
#pragma unroll
        for (int a = 0; a < NAA; a++) {
            float aw = __ldg(&anchors[2 * a]);
            float ah = __ldg(&anchors[2 * a + 1]);
            float inter = fminf(gw, aw) * fminf(gh, ah);
            float un = gw * gh + aw * ah - inter;
            float r = __fdividef(inter, fmaxf(un, EPS12));
            if (r > best) { best = r; bn = a; awb = aw; ahb = ah; }
        }
        gi = (int)gx;
        gj = (int)gy;
        cell = bn * HW + gj * WWW + gi;   // anchor-major cell id
        s_cell[t] = cell;

        // per-band gt list: gt matters only for rows hh in (gy-0.4gh-1, gy+0.4gh)
        float gl = gx - 0.5f * gw, gr = gx + 0.5f * gw;
        float gtp = gy - 0.5f * gh, gbt = gy + 0.5f * gh;
        float ylo = 0.9f * gtp + 0.1f * gbt;  // gy - 0.4*gh
        float yhi = 0.1f * gtp + 0.9f * gbt;  // gy + 0.4*gh
        float gcn = -0.375f * gw * gh;
        GTH gh2;
        gh2.gl = __floats2half2_rn(gl,  gl);
        gh2.gr = __floats2half2_rn(gr,  gr);
        gh2.gt = __floats2half2_rn(gtp, gtp);
        gh2.gb = __floats2half2_rn(gbt, gbt);
        __half2 gcn2 = __floats2half2_rn(gcn, gcn);
#pragma unroll
        for (int bd = 0; bd < BANDS; bd++) {
            float h0 = (float)(bd * RB);
            if (h0 < yhi + 0.01f && h0 + (float)RB > ylo - 0.01f) {
                int pos = atomicAdd(&s_bm[bd], 1);
                g_bgh[nb][bd][pos]  = gh2;
                g_bgc2[nb][bd][pos] = gcn2;
            }
        }
    }
    __syncthreads();

    if (t < ng) {
        // last writer wins for this cell within this nb row
        bool win = true;
        for (int t2 = t + 1; t2 < ng; t2++)
            if (s_cell[t2] == cell) win = false;

        if (win) {
            int b = nb / CC;
            atomicAdd(&g_cnt[b * A4 + cell], 1);
            atomicAdd(&g_tsum[b * A4 + cell], ct);

            const float* ob = out + ((size_t)nb * CHN + bn * 6) * HW + gj * WWW + gi;
            float px = fsigm(ob[0])    + (float)gi;
            float py = fsigm(ob[HW])   + (float)gj;
            float pw = __expf(ob[2 * HW]) * awb;
            float ph = __expf(ob[3 * HW]) * ahb;

            float l  = fmaxf(gx - 0.5f * gw, px - 0.5f * pw);
            float r2 = fminf(gx + 0.5f * gw, px + 0.5f * pw);
            float tp = fmaxf(gy - 0.5f * gh, py - 0.5f * ph);
            float bt = fminf(gy + 0.5f * gh, py + 0.5f * ph);
            float inter = fmaxf(r2 - l, 0.0f) * fmaxf(bt - tp, 0.0f);
            float un = gw * gh + pw * ph - inter;
            float iou = __fdividef(inter, fmaxf(un, EPS12));

            int bd = gj / RB;
            int slot = atomicAdd(&s_bn[bd], 1);
            g_bcell[nb][bd][slot] = cell;
            g_bval[nb][bd][slot][0] = gx - (float)gi;
            g_bval[nb][bd][slot][1] = gy - (float)gj;
            g_bval[nb][bd][slot][2] = __logf(__fdividef(fmaxf(gw, EPS12), awb));
            g_bval[nb][bd][slot][3] = __logf(__fdividef(fmaxf(gh, EPS12), ahb));
            g_bval[nb][bd][slot][4] = iou;
        }
    }
    __syncthreads();
    if (t < BANDS) {
        g_bm[nb][t] = s_bm[t];
        g_bn[nb][t] = s_bn[t];
    }
}

// ---------------------------------------------------------------------------
// Fused dense losses, software-pipelined:
//   Phase A: all 20 LDGs + full fp32 math with DEFAULT targets (overlaps
//            global latency; no shared deps, no syncs).
//   Phase B: gt/assignment shared tables + sync.
//   Phase C: packed-fp16 cull loop.
//   Phase D: rare fixup for assigned cells (avg ~1.3/block) via closed-form
//            deltas; channels reloaded from L1.
//   Phase E: conf epilogue + block reduce.
__global__ void __launch_bounds__(TPB, 11)
k_fused(const float* __restrict__ out,
        const float* __restrict__ anchors,
        float* __restrict__ res) {
    int tid = threadIdx.x;

    if (blockIdx.x < MAIN_BLOCKS) {
        int nb   = blockIdx.x / BANDS;
        int band = blockIdx.x - nb * BANDS;
        int h0   = band * RB;

        __shared__ GTH     s_gh[TT];
        __shared__ __half2 s_gcn2[TT];
        __shared__ int     s_cell[TT];
        __shared__ float   s_val[TT][5];
        __shared__ uint32_t s_bits[57];
        __shared__ float   s_red[3];

        // ---- Phase A: loads + default-target fp32 loss + box packing ----
        __half2 pl2[2], pr2[2], pt2[2], pb2[2], mm2[2];
        float k1f[4], dcvf[4];
        int   gidx[4];
        float contrib = 0.0f;
#pragma unroll
        for (int p = 0; p < 2; p++) {
            float plf[2], prf[2], ptf[2], pbf[2];
#pragma unroll
            for (int j = 0; j < 2; j++) {
                int i = 2 * p + j;
                int c = tid + i * TPB;
                int na = c / (RB * WWW);
                int rem = c - na * (RB * WWW);
                int r = rem / WWW;
                int ww = rem - r * WWW;
                int hh = h0 + r;
                bool live = (c < TILE) && (hh < HHH);
                if (live) {
                    int hw = hh * WWW + ww;
                    gidx[i] = na * HW + hw;
                    const float* ob = out + ((size_t)nb * CHN + na * 6) * HW + hw;
                    float o0 = ob[0], o1 = ob[HW], o2 = ob[2 * HW],
                          o3 = ob[3 * HW], o4 = ob[4 * HW];

                    float x = fsigm(o0), y = fsigm(o1);
                    float aw = __ldg(&anchors[2 * na]);
                    float ah = __ldg(&anchors[2 * na + 1]);
                    float px = x + (float)ww, py = y + (float)hh;
                    float pw = __expf(o2) * aw, ph = __expf(o3) * ah;
                    plf[j] = px - 0.5f * pw; prf[j] = px + 0.5f * pw;
                    ptf[j] = py - 0.5f * ph; pbf[j] = py + 0.5f * ph;
                    k1f[i] = 0.375f * pw * ph;

                    // default targets: tx=ty=0.5, tw=th=0, tconf=0
                    // BCE(sigm(v),t)=softplus(v)-t*v; softplus=-log(1-sigm)
                    contrib += -__logf(1.0f - x) - 0.5f * o0
                               -__logf(1.0f - y) - 0.5f * o1
                               + 0.5f * (o2 * o2 + o3 * o3);
                    dcvf[i] = fsigm(o4);          // conf - 0
                } else {
                    gidx[i] = -1;
                    plf[j] = 100.f; prf[j] = -100.f;   // inert: relu(iw)=0
                    ptf[j] = 100.f; pbf[j] = -100.f;
                    k1f[i] = 1e30f;
                    dcvf[i] = 0.0f;
                }
            }
            pl2[p] = __floats2half2_rn(plf[0], plf[1]);
            pr2[p] = __floats2half2_rn(prf[0], prf[1]);
            pt2[p] = __floats2half2_rn(ptf[0], ptf[1]);
            pb2[p] = __floats2half2_rn(pbf[0], pbf[1]);
            mm2[p] = __floats2half2_rn(-1e30f, -1e30f);
        }

        // ---- Phase B: shared tables ----
        int m    = g_bm[nb][band];
        int nasg = g_bn[nb][band];
        int mp   = ((m + 4) / 5) * 5;

        if (tid < 57) s_bits[tid] = 0u;
        for (int i = tid; i < mp; i += TPB) {
            if (i < m) {
                s_gh[i]   = g_bgh[nb][band][i];
                s_gcn2[i] = g_bgc2[nb][band][i];
            } else {
                GTH z; z.gl = z.gr = z.gt = z.gb = __floats2half2_rn(0.f, 0.f);
                s_gh[i]   = z;
                s_gcn2[i] = __floats2half2_rn(-1e30f, -1e30f);  // -inf: inert
            }
        }
        for (int i = tid; i < nasg * 5; i += TPB)
            (&s_val[0][0])[i] = (&g_bval[nb][band][0][0])[i];
        __syncthreads();
        for (int i = tid; i < nasg; i += TPB) {
            int c = g_bcell[nb][band][i];
            s_cell[i] = c;
            atomicOr(&s_bits[c >> 5], 1u << (c & 31));
        }
        __syncthreads();

        const __half2 zero2 = __floats2half2_rn(0.f, 0.f);

        // ---- Phase C: packed IoU>0.6 cull loop (8 half2 ops/pair/gt) ----
#pragma unroll 5
        for (int t = 0; t < mp; t++) {
            GTH g = s_gh[t];
            __half2 gcn = s_gcn2[t];
#pragma unroll
            for (int p = 0; p < 2; p++) {
                __half2 iw = __hsub2(__hmin2(pr2[p], g.gr), __hmax2(pl2[p], g.gl));
                __half2 ih = __hsub2(__hmin2(pb2[p], g.gb), __hmax2(pt2[p], g.gt));
                mm2[p] = __hmax2(mm2[p], __hfma2(__hmax2(iw, zero2), ih, gcn));
            }
        }

        // ---- Phase D: rare fixup for assigned cells ----
#pragma unroll
        for (int i = 0; i < 4; i++) {
            int idx = gidx[i];
            if (idx >= 0 && (s_bits[idx >> 5] & (1u << (idx & 31)))) {
                float tx = 0.5f, ty = 0.5f, tw = 0.0f, th = 0.0f, tconf = 0.0f;
                for (int k = 0; k < nasg; k++) {
                    if (s_cell[k] == idx) {
                        tx = s_val[k][0]; ty = s_val[k][1];
                        tw = s_val[k][2]; th = s_val[k][3];
                        tconf = s_val[k][4];
                    }
                }
                int na = idx / HW;
                int hw = idx - na * HW;
                const float* ob = out + ((size_t)nb * CHN + na * 6) * HW + hw;
                float o0 = ob[0], o1 = ob[HW], o2 = ob[2 * HW], o3 = ob[3 * HW];
                // deltas: actual - default
                contrib += (0.5f - tx) * o0 + (0.5f - ty) * o1
                         + 0.5f * tw * tw - o2 * tw
                         + 0.5f * th * th - o3 * th;
                dcvf[i] -= tconf;         // conf - tconf
                k1f[i]  = 1e30f;          // assigned: conf term always on
            }
        }

        // ---- Phase E: conf epilogue (fp32 compare) + reduce ----
        float2 m0 = __half22float2(mm2[0]);
        float2 m1 = __half22float2(mm2[1]);
        float mmf[4] = {m0.x, m0.y, m1.x, m1.y};
#pragma unroll
        for (int i = 0; i < 4; i++) {
            float dc = (mmf[i] > k1f[i]) ? 0.0f : dcvf[i];
            contrib += 0.5f * dc * dc;
        }

#pragma unroll
        for (int o = 16; o > 0; o >>= 1)
            contrib += __shfl_down_sync(0xffffffffu, contrib, o);
        if ((tid & 31) == 0) s_red[tid >> 5] = contrib;
        __syncthreads();
        if (tid == 0)
            atomicAdd(&g_accf[0], s_red[0] + s_red[1] + s_red[2]);
    } else {
        // ---- class-loss blocks (self-cleaning: reset g_cnt/g_tsum) ----
        int idx = (blockIdx.x - MAIN_BLOCKS) * TPB + tid;
        float nll = 0.0f, ns = 0.0f;
        if (idx < CLS_N) {
            int cnt = g_cnt[idx];
            if (cnt != 0) {
                float tsum = g_tsum[idx];
                g_cnt[idx] = 0;
                g_tsum[idx] = 0.0f;
                if (cnt == 1) {
                    int b  = idx / A4;
                    int a4 = idx - b * A4;
                    int na = a4 / HW;
                    int hw = a4 - na * HW;
                    int label = (int)tsum;
                    size_t obase = ((size_t)b * CC * CHN + na * 6 + 5) * HW + hw;
                    float mv = -1e30f, s = 0.0f, llab = 0.0f;
#pragma unroll
                    for (int c = 0; c < CC; c++) {
                        float l = out[obase + (size_t)c * CHN * HW];
                        if (c == label) llab = l;
                        if (l > mv) { s = s * __expf(mv - l) + 1.0f; mv = l; }
                        else        { s += __expf(l - mv); }
                    }
                    nll = mv + __logf(s) - llab;
                    ns  = 1.0f;
                }
            }
        }
#pragma unroll
        for (int o = 16; o > 0; o >>= 1) {
            nll += __shfl_down_sync(0xffffffffu, nll, o);
            ns  += __shfl_down_sync(0xffffffffu, ns,  o);
        }
        __shared__ float s_n[3], s_c[3];
        if ((tid & 31) == 0) { s_n[tid >> 5] = nll; s_c[tid >> 5] = ns; }
        __syncthreads();
        if (tid == 0) {
            float a = s_n[0] + s_n[1] + s_n[2];
            float bsum = s_c[0] + s_c[1] + s_c[2];
            if (a != 0.0f)    atomicAdd(&g_accf[1], a);
            if (bsum != 0.0f) atomicAdd(&g_accf[2], bsum);
        }
    }

    // ---- last-block final combine (also resets g_accf for next replay) ----
    if (tid == 0) {
        __threadfence();
        unsigned int old = atomicAdd(&g_done, 1u);
        if (old == TOTB - 1) {
            float a0 = atomicExch(&g_accf[0], 0.0f);
            float a1 = atomicExch(&g_accf[1], 0.0f);
            float a2 = atomicExch(&g_accf[2], 0.0f);
            double N = (double)NBB * (double)A4;
            res[0] = (float)((double)a0 / N +
                             (double)a1 / fmax((double)a2, 1.0));
            g_done = 0;
        }
    }
}

// ---------------------------------------------------------------------------
extern "C" void kernel_launch(void* const* d_in, const int* in_sizes, int n_in,
                              void* d_out, int out_size) {
    const float* out_t   = (const float*)d_in[0];
    const float* target  = (const float*)d_in[1];
    const float* anchors = (const float*)d_in[2];
    float* res = (float*)d_out;

    k_assign<<<NBB, 64>>>(out_t, target, anchors);
    k_fused<<<TOTB, TPB>>>(out_t, anchors, res);
}